// round 13
// baseline (speedup 1.0000x reference)
#include <cuda_runtime.h>
#include <cuda_bf16.h>
#include <math.h>
#include <stdint.h>

// LogMap via matrix polynomial on the tensor pipe (portable mma.sync m16n8k16 bf16).
// log(X) = p(S), S=(X-m I)/h on [1,6.8]; p = deg-8 Chebyshev fit.
// Sastre 3-product scheme: Z=S^2; W=Z*V, V=Z+c1*S; p = q*r + lin.
// Fragment-reuse: A-frag footprint == acc footprint, so
//   - V-pass uses S from P1's A-frags (no SMEM reads)
//   - fused pass takes Z from A-frags, loads only V, reconstructs S=(V-Z)/c1
// Two 8KB buffer pairs (32KB): pair1 = S, pair2 = V -> r.
// 1 matrix/CTA, 4 warps; launch_bounds(128,5) -> 5 CTAs/SM (20 warps,
// the measured concurrency/ILP optimum). Product is software-pipelined.

#define DEG 8
struct Coeffs {
    float mshift, invh, c1, inv_c1;
    float qa, qb, qc, qd;       // q = qa*W + qb*Z + qc*S + qd*I   (scaled 1/gam)
    float ra, rb;               // r = ra*W + rb*S                 (scaled gam)
    float f0, f1, f2;           // lin = f0*I + f1*S + f2*Z
};

#define SH 0
#define SL 8192
#define VH 16384
#define VL 24576
#define SMEM_TOTAL 32768

__device__ __forceinline__ uint32_t smem_u32(const void* p) {
    uint32_t a;
    asm("{ .reg .u64 t; cvta.to.shared.u64 t, %1; cvt.u32.u64 %0, t; }"
        : "=r"(a) : "l"(p));
    return a;
}

__device__ __forceinline__ uint32_t swoff(int r, int cb) {
    return (uint32_t)(r * 128 + ((((cb >> 4) ^ (r & 7))) << 4) + (cb & 15));
}

__device__ __forceinline__ void sts32(uint32_t a, uint32_t v) {
    asm volatile("st.shared.b32 [%0], %1;" :: "r"(a), "r"(v));
}
__device__ __forceinline__ void sts128(uint32_t a, uint32_t x, uint32_t y,
                                       uint32_t z, uint32_t w) {
    asm volatile("st.shared.v4.b32 [%0], {%1,%2,%3,%4};"
                 :: "r"(a), "r"(x), "r"(y), "r"(z), "r"(w));
}

#define LDMX4(d, addr) \
    asm volatile("ldmatrix.sync.aligned.m8n8.x4.shared.b16 {%0,%1,%2,%3}, [%4];" \
        : "=r"((d)[0]), "=r"((d)[1]), "=r"((d)[2]), "=r"((d)[3]) : "r"(addr))

#define LDMX4T(d, addr) \
    asm volatile("ldmatrix.sync.aligned.m8n8.x4.trans.shared.b16 {%0,%1,%2,%3}, [%4];" \
        : "=r"((d)[0]), "=r"((d)[1]), "=r"((d)[2]), "=r"((d)[3]) : "r"(addr))

#define MMA(c, a, b0v, b1v) \
    asm volatile("mma.sync.aligned.m16n8k16.row.col.f32.bf16.bf16.f32 " \
        "{%0,%1,%2,%3}, {%4,%5,%6,%7}, {%8,%9}, {%0,%1,%2,%3};" \
        : "+f"((c)[0]), "+f"((c)[1]), "+f"((c)[2]), "+f"((c)[3]) \
        : "r"((a)[0]), "r"((a)[1]), "r"((a)[2]), "r"((a)[3]), "r"(b0v), "r"(b1v))

__device__ __forceinline__ uint32_t pk(float a, float b) {
    __nv_bfloat162 t = __floats2bfloat162_rn(a, b);
    return *reinterpret_cast<uint32_t*>(&t);
}
__device__ __forceinline__ float2 upk(uint32_t u) {
    __nv_bfloat162 t = *reinterpret_cast<__nv_bfloat162*>(&u);
    return __bfloat1622float2(t);
}
__device__ __forceinline__ float bhi(float v) {
    return __bfloat162float(__float2bfloat16_rn(v));
}

__global__ void __launch_bounds__(128, 5)
logmap_mma_kernel(const float* __restrict__ X, float* __restrict__ out, Coeffs cf)
{
    extern __shared__ char smraw[];
    const uint32_t sb = smem_u32(smraw);
    const int tid = threadIdx.x;
    const int w = tid >> 5;              // warp owns rows [16w, 16w+16)
    const int l = tid & 31;
    const int sr = 16 * w;
    const int lq = l >> 2, lr = l & 3;
    const int lmr = l & 15;
    const int lmc16 = (l >> 4) & 1;
    const int key = lmr & 7;
    const size_t mb = (size_t)blockIdx.x * 4096;

    uint32_t colx[4];
    #pragma unroll
    for (int j = 0; j < 4; j++) colx[j] = (uint32_t)((((2*j + lmc16) ^ key)) << 4);
    const uint32_t arow = (uint32_t)((sr + lmr) * 128);
    const int er0 = sr + lq, er1 = er0 + 8;

    // ---- load X (half-row/thread), S = (X - m I)/h, write S hi/lo -> pair1 ----
    {
        const int row = sr + (l >> 1);
        const int c0 = 32 * (l & 1);
        const float4* xr = (const float4*)(X + mb + (size_t)row * 64 + c0);
        float v[32];
        #pragma unroll
        for (int q = 0; q < 8; q++) {
            float4 f = xr[q];
            v[4*q] = f.x; v[4*q+1] = f.y; v[4*q+2] = f.z; v[4*q+3] = f.w;
        }
        #pragma unroll
        for (int i = 0; i < 32; i++) {
            float t = v[i];
            if (c0 + i == row) t -= cf.mshift;
            v[i] = t * cf.invh;
        }
        #pragma unroll
        for (int q = 0; q < 4; q++) {
            uint32_t o = swoff(row, 2 * c0 + 16 * q);
            const float* p = v + 8 * q;
            sts128(sb + SH + o, pk(p[0], p[1]), pk(p[2], p[3]),
                                pk(p[4], p[5]), pk(p[6], p[7]));
            sts128(sb + SL + o,
                   pk(p[0]-bhi(p[0]), p[1]-bhi(p[1])),
                   pk(p[2]-bhi(p[2]), p[3]-bhi(p[3])),
                   pk(p[4]-bhi(p[4]), p[5]-bhi(p[5])),
                   pk(p[6]-bhi(p[6]), p[7]-bhi(p[7])));
        }
    }
    __syncthreads();                       // (1) S visible

    float acc[8][4];
    uint32_t ah[4][4], al[4][4];

    auto zacc = [&] {
        #pragma unroll
        for (int n = 0; n < 8; n++)
            #pragma unroll
            for (int q = 0; q < 4; q++) acc[n][q] = 0.f;
    };

    auto cvtA = [&] {
        #pragma unroll
        for (int kk = 0; kk < 4; kk++) {
            float c00 = acc[2*kk][0],   c01 = acc[2*kk][1];
            float c02 = acc[2*kk][2],   c03 = acc[2*kk][3];
            float d00 = acc[2*kk+1][0], d01 = acc[2*kk+1][1];
            float d02 = acc[2*kk+1][2], d03 = acc[2*kk+1][3];
            ah[kk][0] = pk(c00, c01); ah[kk][1] = pk(c02, c03);
            ah[kk][2] = pk(d00, d01); ah[kk][3] = pk(d02, d03);
            al[kk][0] = pk(c00 - bhi(c00), c01 - bhi(c01));
            al[kk][1] = pk(c02 - bhi(c02), c03 - bhi(c03));
            al[kk][2] = pk(d00 - bhi(d00), d01 - bhi(d01));
            al[kk][3] = pk(d02 - bhi(d02), d03 - bhi(d03));
        }
    };

    // acc += A(frags)*B(smem hi/lo), software-pipelined over j
    auto product = [&](uint32_t bhBase, uint32_t blBase) {
        #pragma unroll
        for (int kk = 0; kk < 4; kk++) {
            const uint32_t kbo = (uint32_t)((16*kk + lmr) * 128);
            uint32_t bb[2][2][4];
            LDMX4T(bb[0][0], bhBase + kbo + colx[0]);
            LDMX4T(bb[0][1], blBase + kbo + colx[0]);
            #pragma unroll
            for (int j = 0; j < 4; j++) {
                const int cur = j & 1, nxt = cur ^ 1;
                if (j < 3) {
                    LDMX4T(bb[nxt][0], bhBase + kbo + colx[j+1]);
                    LDMX4T(bb[nxt][1], blBase + kbo + colx[j+1]);
                }
                MMA(acc[2*j],   ah[kk], bb[cur][0][0], bb[cur][0][1]);
                MMA(acc[2*j+1], ah[kk], bb[cur][0][2], bb[cur][0][3]);
                MMA(acc[2*j],   al[kk], bb[cur][0][0], bb[cur][0][1]);
                MMA(acc[2*j+1], al[kk], bb[cur][0][2], bb[cur][0][3]);
                MMA(acc[2*j],   ah[kk], bb[cur][1][0], bb[cur][1][1]);
                MMA(acc[2*j+1], ah[kk], bb[cur][1][2], bb[cur][1][3]);
            }
        }
    };

    // ---- P1: Z = S*S (A frags = S from smem) ----
    #pragma unroll
    for (int kk = 0; kk < 4; kk++) {
        uint32_t o = arow + colx[kk];
        LDMX4(ah[kk], sb + SH + o);
        LDMX4(al[kk], sb + SL + o);
    }
    zacc();
    product(sb + SH, sb + SL);

    // ---- V = Z(acc) + c1*S(frags) -> pair2 ; S from ah/al (frag==acc layout) ----
    #pragma unroll
    for (int kk = 0; kk < 4; kk++)
        #pragma unroll
        for (int q = 0; q < 4; q++) {
            float2 s1 = upk(ah[kk][q]), s2 = upk(al[kk][q]);
            float sx = s1.x + s2.x, sy = s1.y + s2.y;
            int n = 2 * kk + (q >> 1), c = (q & 1) * 2;
            int row = (q & 1) ? er1 : er0;
            float v0 = acc[n][c]     + cf.c1 * sx;
            float v1 = acc[n][c + 1] + cf.c1 * sy;
            uint32_t so = swoff(row, 16 * n + 4 * lr);
            sts32(sb + VH + so, pk(v0, v1));
            sts32(sb + VL + so, pk(v0 - bhi(v0), v1 - bhi(v1)));
        }
    cvtA();                                // A <- Z (overwrites S frags)
    __syncthreads();                       // (2) V visible

    // ---- P2: W = Z*V ----
    zacc();
    product(sb + VH, sb + VL);
    __syncthreads();                       // (3) all P2 reads of V done

    // ---- fused pass: q -> frags (in place over Z), r -> pair2, lin -> acc ----
    // Z from frags; V loaded; S = (V - Z)/c1.
    #pragma unroll
    for (int g = 0; g < 4; g++) {
        uint32_t vh[4], vl[4];
        uint32_t o = arow + colx[g];
        LDMX4(vh, sb + VH + o);
        LDMX4(vl, sb + VL + o);
        #pragma unroll
        for (int q = 0; q < 4; q++) {
            float2 z1 = upk(ah[g][q]), z2 = upk(al[g][q]);
            float2 v1 = upk(vh[q]),    v2 = upk(vl[q]);
            float zx = z1.x + z2.x, zy = z1.y + z2.y;
            float vx = v1.x + v2.x, vy = v1.y + v2.y;
            float sx = (vx - zx) * cf.inv_c1, sy = (vy - zy) * cf.inv_c1;
            int n = 2 * g + (q >> 1), c = (q & 1) * 2;
            int row = (q & 1) ? er1 : er0;
            int col0 = 8 * n + 2 * lr;
            float w0 = acc[n][c], w1 = acc[n][c + 1];
            // q (in place over Z frags)
            float q0 = cf.qa * w0 + cf.qb * zx + cf.qc * sx;
            float q1 = cf.qa * w1 + cf.qb * zy + cf.qc * sy;
            if (col0 == row)     q0 += cf.qd;
            if (col0 + 1 == row) q1 += cf.qd;
            ah[g][q] = pk(q0, q1);
            al[g][q] = pk(q0 - bhi(q0), q1 - bhi(q1));
            // r -> pair2
            float r0 = cf.ra * w0 + cf.rb * sx;
            float r1 = cf.ra * w1 + cf.rb * sy;
            uint32_t so = swoff(row, 16 * n + 4 * lr);
            sts32(sb + VH + so, pk(r0, r1));
            sts32(sb + VL + so, pk(r0 - bhi(r0), r1 - bhi(r1)));
            // lin -> acc (P3 init)
            float f0 = cf.f1 * sx + cf.f2 * zx;
            float f1 = cf.f1 * sy + cf.f2 * zy;
            if (col0 == row)     f0 += cf.f0;
            if (col0 + 1 == row) f1 += cf.f0;
            acc[n][c] = f0;
            acc[n][c + 1] = f1;
        }
    }
    __syncthreads();                       // (4) r visible

    // ---- P3: P = lin + q*r ----
    product(sb + VH, sb + VL);

    // ---- store result (fp32) ----
    #pragma unroll
    for (int n = 0; n < 8; n++) {
        int c0 = 8 * n + 2 * lr;
        *(float2*)(out + mb + (size_t)er0 * 64 + c0) =
            make_float2(acc[n][0], acc[n][1]);
        *(float2*)(out + mb + (size_t)er1 * 64 + c0) =
            make_float2(acc[n][2], acc[n][3]);
    }
}

extern "C" void kernel_launch(void* const* d_in, const int* in_sizes, int n_in,
                              void* d_out, int out_size)
{
    const float* X = (const float*)d_in[0];
    float* out = (float*)d_out;
    const int nmat = in_sizes[0] >> 12;

    Coeffs cf;
    {
        // Chebyshev coeffs of log on [1, 6.8] -> monomial p0..p8
        const double a = 1.0, b = 6.8;
        const double m = 0.5 * (a + b);
        const double hh = 0.5 * (b - a);
        const double w = hh / m;
        const double rho = (1.0 - sqrt(1.0 - w * w)) / w;

        double c[DEG + 1];
        c[0] = log(m) - log1p(rho * rho);
        double rp = 1.0;
        for (int k = 1; k <= DEG; k++) {
            rp *= rho;
            c[k] = 2.0 * ((k & 1) ? rp : -rp) / (double)k;
        }
        double p[DEG + 1], Tm2[DEG + 1], Tm1[DEG + 1], Tc[DEG + 1];
        for (int i = 0; i <= DEG; i++) { p[i] = 0.0; Tm2[i] = 0.0; Tm1[i] = 0.0; }
        Tm2[0] = 1.0; p[0] += c[0];
        Tm1[1] = 1.0; p[1] += c[1];
        for (int k = 2; k <= DEG; k++) {
            for (int i = 0; i <= DEG; i++) Tc[i] = 0.0;
            for (int i = 0; i < k; i++) Tc[i + 1] += 2.0 * Tm1[i];
            for (int i = 0; i <= k - 2; i++) Tc[i] -= Tm2[i];
            for (int i = 0; i <= k; i++) p[i] += c[k] * Tc[i];
            for (int i = 0; i <= DEG; i++) { Tm2[i] = Tm1[i]; Tm1[i] = Tc[i]; }
        }

        // Sastre 3-product scheme
        const double c1 = p[7] / (2.0 * p[8]);
        const double c3 = p[6] - p[8] * c1 * c1;
        const double c5 = p[4] - c1 * p[5] + c1 * c1 * c3;
        const double c7 = (p[3] - c1 * c5) / c3;
        const double c4 = p[5] - p[8] * c7 - c3 * c1;
        const double c10 = p[2] - c4 * c7;
        const double c11 = p[1] - c5 * c7;
        const double c12 = p[0];

        // balance q, r
        double maxq = 0.0, maxr = 0.0;
        for (int i = 0; i <= 2000; i++) {
            double t = -1.0 + 2.0 * i / 2000.0;
            double W = t*t*t*t + c1 * t*t*t;
            double qv = p[8]*W + c3*t*t + c4*t + c5;
            double rv = W + c7*t;
            if (fabs(qv) > maxq) maxq = fabs(qv);
            if (fabs(rv) > maxr) maxr = fabs(rv);
        }
        const double gam = sqrt(maxq / maxr);

        cf.mshift = (float)m;
        cf.invh = (float)(1.0 / hh);
        cf.c1 = (float)c1;
        cf.inv_c1 = (float)(1.0 / c1);
        cf.qa = (float)(p[8] / gam);
        cf.qb = (float)(c3 / gam);
        cf.qc = (float)(c4 / gam);
        cf.qd = (float)(c5 / gam);
        cf.ra = (float)gam;
        cf.rb = (float)(gam * c7);
        cf.f0 = (float)c12;
        cf.f1 = (float)c11;
        cf.f2 = (float)c10;
    }

    cudaFuncSetAttribute(logmap_mma_kernel,
                         cudaFuncAttributeMaxDynamicSharedMemorySize, SMEM_TOTAL);
    logmap_mma_kernel<<<nmat, 128, SMEM_TOTAL>>>(X, out, cf);
}

// round 14
// speedup vs baseline: 1.0110x; 1.0110x over previous
#include <cuda_runtime.h>
#include <cuda_bf16.h>
#include <math.h>
#include <stdint.h>

// LogMap via matrix polynomial on the tensor pipe (portable mma.sync m16n8k16 bf16).
// log(X) = p(S), S=(X-m I)/h on [1,6.8]; p = deg-8 Chebyshev fit.
// Sastre 3-product scheme: Z=S^2; W=Z*V, V=Z+c1*S; p = q*r + lin.
// Z never stored (lives in acc -> A-frags). Fragment-reuse passes:
//   V-pass: S taken from P1's A-frags (no SMEM reads)
//   fused pass: Z from A-frags, loads only V, S=(V-Z)/c1
// Product is NOT software-pipelined (4 live B regs) -- R13 showed the
// 16-reg pipelined version spills under the 5-CTA cap (L2 23->36%).
// Two 8KB buffer pairs (32KB). 4 warps/CTA; launch_bounds(128,5) = 20 warps/SM.

#define DEG 8
struct Coeffs {
    float mshift, invh, c1, inv_c1;
    float qa, qb, qc, qd;       // q = qa*W + qb*Z + qc*S + qd*I   (scaled 1/gam)
    float ra, rb;               // r = ra*W + rb*S                 (scaled gam)
    float f0, f1, f2;           // lin = f0*I + f1*S + f2*Z
};

#define SH 0
#define SL 8192
#define VH 16384
#define VL 24576
#define SMEM_TOTAL 32768

__device__ __forceinline__ uint32_t smem_u32(const void* p) {
    uint32_t a;
    asm("{ .reg .u64 t; cvta.to.shared.u64 t, %1; cvt.u32.u64 %0, t; }"
        : "=r"(a) : "l"(p));
    return a;
}

__device__ __forceinline__ uint32_t swoff(int r, int cb) {
    return (uint32_t)(r * 128 + ((((cb >> 4) ^ (r & 7))) << 4) + (cb & 15));
}

__device__ __forceinline__ void sts32(uint32_t a, uint32_t v) {
    asm volatile("st.shared.b32 [%0], %1;" :: "r"(a), "r"(v));
}
__device__ __forceinline__ void sts128(uint32_t a, uint32_t x, uint32_t y,
                                       uint32_t z, uint32_t w) {
    asm volatile("st.shared.v4.b32 [%0], {%1,%2,%3,%4};"
                 :: "r"(a), "r"(x), "r"(y), "r"(z), "r"(w));
}

#define LDMX4(d, addr) \
    asm volatile("ldmatrix.sync.aligned.m8n8.x4.shared.b16 {%0,%1,%2,%3}, [%4];" \
        : "=r"((d)[0]), "=r"((d)[1]), "=r"((d)[2]), "=r"((d)[3]) : "r"(addr))

#define LDMX4T(d, addr) \
    asm volatile("ldmatrix.sync.aligned.m8n8.x4.trans.shared.b16 {%0,%1,%2,%3}, [%4];" \
        : "=r"((d)[0]), "=r"((d)[1]), "=r"((d)[2]), "=r"((d)[3]) : "r"(addr))

#define MMA(c, a, b0v, b1v) \
    asm volatile("mma.sync.aligned.m16n8k16.row.col.f32.bf16.bf16.f32 " \
        "{%0,%1,%2,%3}, {%4,%5,%6,%7}, {%8,%9}, {%0,%1,%2,%3};" \
        : "+f"((c)[0]), "+f"((c)[1]), "+f"((c)[2]), "+f"((c)[3]) \
        : "r"((a)[0]), "r"((a)[1]), "r"((a)[2]), "r"((a)[3]), "r"(b0v), "r"(b1v))

__device__ __forceinline__ uint32_t pk(float a, float b) {
    __nv_bfloat162 t = __floats2bfloat162_rn(a, b);
    return *reinterpret_cast<uint32_t*>(&t);
}
__device__ __forceinline__ float2 upk(uint32_t u) {
    __nv_bfloat162 t = *reinterpret_cast<__nv_bfloat162*>(&u);
    return __bfloat1622float2(t);
}
__device__ __forceinline__ float bhi(float v) {
    return __bfloat162float(__float2bfloat16_rn(v));
}

__global__ void __launch_bounds__(128, 5)
logmap_mma_kernel(const float* __restrict__ X, float* __restrict__ out, Coeffs cf)
{
    extern __shared__ char smraw[];
    const uint32_t sb = smem_u32(smraw);
    const int tid = threadIdx.x;
    const int w = tid >> 5;              // warp owns rows [16w, 16w+16)
    const int l = tid & 31;
    const int sr = 16 * w;
    const int lq = l >> 2, lr = l & 3;
    const int lmr = l & 15;
    const int lmc16 = (l >> 4) & 1;
    const int key = lmr & 7;
    const size_t mb = (size_t)blockIdx.x * 4096;

    uint32_t colx[4];
    #pragma unroll
    for (int j = 0; j < 4; j++) colx[j] = (uint32_t)((((2*j + lmc16) ^ key)) << 4);
    const uint32_t arow = (uint32_t)((sr + lmr) * 128);
    const int er0 = sr + lq, er1 = er0 + 8;

    // ---- load X (half-row/thread), S = (X - m I)/h, write S hi/lo -> pair1 ----
    {
        const int row = sr + (l >> 1);
        const int c0 = 32 * (l & 1);
        const float4* xr = (const float4*)(X + mb + (size_t)row * 64 + c0);
        float v[32];
        #pragma unroll
        for (int q = 0; q < 8; q++) {
            float4 f = xr[q];
            v[4*q] = f.x; v[4*q+1] = f.y; v[4*q+2] = f.z; v[4*q+3] = f.w;
        }
        #pragma unroll
        for (int i = 0; i < 32; i++) {
            float t = v[i];
            if (c0 + i == row) t -= cf.mshift;
            v[i] = t * cf.invh;
        }
        #pragma unroll
        for (int q = 0; q < 4; q++) {
            uint32_t o = swoff(row, 2 * c0 + 16 * q);
            const float* p = v + 8 * q;
            sts128(sb + SH + o, pk(p[0], p[1]), pk(p[2], p[3]),
                                pk(p[4], p[5]), pk(p[6], p[7]));
            sts128(sb + SL + o,
                   pk(p[0]-bhi(p[0]), p[1]-bhi(p[1])),
                   pk(p[2]-bhi(p[2]), p[3]-bhi(p[3])),
                   pk(p[4]-bhi(p[4]), p[5]-bhi(p[5])),
                   pk(p[6]-bhi(p[6]), p[7]-bhi(p[7])));
        }
    }
    __syncthreads();                       // (1) S visible

    float acc[8][4];
    uint32_t ah[4][4], al[4][4];

    auto zacc = [&] {
        #pragma unroll
        for (int n = 0; n < 8; n++)
            #pragma unroll
            for (int q = 0; q < 4; q++) acc[n][q] = 0.f;
    };

    auto cvtA = [&] {
        #pragma unroll
        for (int kk = 0; kk < 4; kk++) {
            float c00 = acc[2*kk][0],   c01 = acc[2*kk][1];
            float c02 = acc[2*kk][2],   c03 = acc[2*kk][3];
            float d00 = acc[2*kk+1][0], d01 = acc[2*kk+1][1];
            float d02 = acc[2*kk+1][2], d03 = acc[2*kk+1][3];
            ah[kk][0] = pk(c00, c01); ah[kk][1] = pk(c02, c03);
            ah[kk][2] = pk(d00, d01); ah[kk][3] = pk(d02, d03);
            al[kk][0] = pk(c00 - bhi(c00), c01 - bhi(c01));
            al[kk][1] = pk(c02 - bhi(c02), c03 - bhi(c03));
            al[kk][2] = pk(d00 - bhi(d00), d01 - bhi(d01));
            al[kk][3] = pk(d02 - bhi(d02), d03 - bhi(d03));
        }
    };

    // acc += A(frags)*B(smem hi/lo); single b[4] temp (no spills)
    auto product = [&](uint32_t bhBase, uint32_t blBase) {
        #pragma unroll
        for (int kk = 0; kk < 4; kk++) {
            const uint32_t kbo = (uint32_t)((16*kk + lmr) * 128);
            #pragma unroll
            for (int j = 0; j < 4; j++) {
                uint32_t o = kbo + colx[j];
                uint32_t b[4];
                LDMX4T(b, bhBase + o);
                MMA(acc[2*j],   ah[kk], b[0], b[1]);
                MMA(acc[2*j+1], ah[kk], b[2], b[3]);
                MMA(acc[2*j],   al[kk], b[0], b[1]);
                MMA(acc[2*j+1], al[kk], b[2], b[3]);
                LDMX4T(b, blBase + o);
                MMA(acc[2*j],   ah[kk], b[0], b[1]);
                MMA(acc[2*j+1], ah[kk], b[2], b[3]);
            }
        }
    };

    // ---- P1: Z = S*S (A frags = S from smem) ----
    #pragma unroll
    for (int kk = 0; kk < 4; kk++) {
        uint32_t o = arow + colx[kk];
        LDMX4(ah[kk], sb + SH + o);
        LDMX4(al[kk], sb + SL + o);
    }
    zacc();
    product(sb + SH, sb + SL);

    // ---- V = Z(acc) + c1*S(frags) -> pair2 ; S from ah/al (frag==acc layout) ----
    #pragma unroll
    for (int kk = 0; kk < 4; kk++)
        #pragma unroll
        for (int q = 0; q < 4; q++) {
            float2 s1 = upk(ah[kk][q]), s2 = upk(al[kk][q]);
            float sx = s1.x + s2.x, sy = s1.y + s2.y;
            int n = 2 * kk + (q >> 1), c = (q & 1) * 2;
            int row = (q & 1) ? er1 : er0;
            float v0 = acc[n][c]     + cf.c1 * sx;
            float v1 = acc[n][c + 1] + cf.c1 * sy;
            uint32_t so = swoff(row, 16 * n + 4 * lr);
            sts32(sb + VH + so, pk(v0, v1));
            sts32(sb + VL + so, pk(v0 - bhi(v0), v1 - bhi(v1)));
        }
    cvtA();                                // A <- Z (overwrites S frags)
    __syncthreads();                       // (2) V visible

    // ---- P2: W = Z*V ----
    zacc();
    product(sb + VH, sb + VL);
    __syncthreads();                       // (3) all P2 reads of V done

    // ---- fused pass: q -> frags (in place over Z), r -> pair2, lin -> acc ----
    // Z from frags; V loaded; S = (V - Z)/c1.
    #pragma unroll
    for (int g = 0; g < 4; g++) {
        uint32_t vh[4], vl[4];
        uint32_t o = arow + colx[g];
        LDMX4(vh, sb + VH + o);
        LDMX4(vl, sb + VL + o);
        #pragma unroll
        for (int q = 0; q < 4; q++) {
            float2 z1 = upk(ah[g][q]), z2 = upk(al[g][q]);
            float2 v1 = upk(vh[q]),    v2 = upk(vl[q]);
            float zx = z1.x + z2.x, zy = z1.y + z2.y;
            float vx = v1.x + v2.x, vy = v1.y + v2.y;
            float sx = (vx - zx) * cf.inv_c1, sy = (vy - zy) * cf.inv_c1;
            int n = 2 * g + (q >> 1), c = (q & 1) * 2;
            int row = (q & 1) ? er1 : er0;
            int col0 = 8 * n + 2 * lr;
            float w0 = acc[n][c], w1 = acc[n][c + 1];
            // q (in place over Z frags)
            float q0 = cf.qa * w0 + cf.qb * zx + cf.qc * sx;
            float q1 = cf.qa * w1 + cf.qb * zy + cf.qc * sy;
            if (col0 == row)     q0 += cf.qd;
            if (col0 + 1 == row) q1 += cf.qd;
            ah[g][q] = pk(q0, q1);
            al[g][q] = pk(q0 - bhi(q0), q1 - bhi(q1));
            // r -> pair2
            float r0 = cf.ra * w0 + cf.rb * sx;
            float r1 = cf.ra * w1 + cf.rb * sy;
            uint32_t so = swoff(row, 16 * n + 4 * lr);
            sts32(sb + VH + so, pk(r0, r1));
            sts32(sb + VL + so, pk(r0 - bhi(r0), r1 - bhi(r1)));
            // lin -> acc (P3 init)
            float f0 = cf.f1 * sx + cf.f2 * zx;
            float f1 = cf.f1 * sy + cf.f2 * zy;
            if (col0 == row)     f0 += cf.f0;
            if (col0 + 1 == row) f1 += cf.f0;
            acc[n][c] = f0;
            acc[n][c + 1] = f1;
        }
    }
    __syncthreads();                       // (4) r visible

    // ---- P3: P = lin + q*r ----
    product(sb + VH, sb + VL);

    // ---- store result (fp32) ----
    #pragma unroll
    for (int n = 0; n < 8; n++) {
        int c0 = 8 * n + 2 * lr;
        *(float2*)(out + mb + (size_t)er0 * 64 + c0) =
            make_float2(acc[n][0], acc[n][1]);
        *(float2*)(out + mb + (size_t)er1 * 64 + c0) =
            make_float2(acc[n][2], acc[n][3]);
    }
}

extern "C" void kernel_launch(void* const* d_in, const int* in_sizes, int n_in,
                              void* d_out, int out_size)
{
    const float* X = (const float*)d_in[0];
    float* out = (float*)d_out;
    const int nmat = in_sizes[0] >> 12;

    Coeffs cf;
    {
        // Chebyshev coeffs of log on [1, 6.8] -> monomial p0..p8
        const double a = 1.0, b = 6.8;
        const double m = 0.5 * (a + b);
        const double hh = 0.5 * (b - a);
        const double w = hh / m;
        const double rho = (1.0 - sqrt(1.0 - w * w)) / w;

        double c[DEG + 1];
        c[0] = log(m) - log1p(rho * rho);
        double rp = 1.0;
        for (int k = 1; k <= DEG; k++) {
            rp *= rho;
            c[k] = 2.0 * ((k & 1) ? rp : -rp) / (double)k;
        }
        double p[DEG + 1], Tm2[DEG + 1], Tm1[DEG + 1], Tc[DEG + 1];
        for (int i = 0; i <= DEG; i++) { p[i] = 0.0; Tm2[i] = 0.0; Tm1[i] = 0.0; }
        Tm2[0] = 1.0; p[0] += c[0];
        Tm1[1] = 1.0; p[1] += c[1];
        for (int k = 2; k <= DEG; k++) {
            for (int i = 0; i <= DEG; i++) Tc[i] = 0.0;
            for (int i = 0; i < k; i++) Tc[i + 1] += 2.0 * Tm1[i];
            for (int i = 0; i <= k - 2; i++) Tc[i] -= Tm2[i];
            for (int i = 0; i <= k; i++) p[i] += c[k] * Tc[i];
            for (int i = 0; i <= DEG; i++) { Tm2[i] = Tm1[i]; Tm1[i] = Tc[i]; }
        }

        // Sastre 3-product scheme
        const double c1 = p[7] / (2.0 * p[8]);
        const double c3 = p[6] - p[8] * c1 * c1;
        const double c5 = p[4] - c1 * p[5] + c1 * c1 * c3;
        const double c7 = (p[3] - c1 * c5) / c3;
        const double c4 = p[5] - p[8] * c7 - c3 * c1;
        const double c10 = p[2] - c4 * c7;
        const double c11 = p[1] - c5 * c7;
        const double c12 = p[0];

        // balance q, r
        double maxq = 0.0, maxr = 0.0;
        for (int i = 0; i <= 2000; i++) {
            double t = -1.0 + 2.0 * i / 2000.0;
            double W = t*t*t*t + c1 * t*t*t;
            double qv = p[8]*W + c3*t*t + c4*t + c5;
            double rv = W + c7*t;
            if (fabs(qv) > maxq) maxq = fabs(qv);
            if (fabs(rv) > maxr) maxr = fabs(rv);
        }
        const double gam = sqrt(maxq / maxr);

        cf.mshift = (float)m;
        cf.invh = (float)(1.0 / hh);
        cf.c1 = (float)c1;
        cf.inv_c1 = (float)(1.0 / c1);
        cf.qa = (float)(p[8] / gam);
        cf.qb = (float)(c3 / gam);
        cf.qc = (float)(c4 / gam);
        cf.qd = (float)(c5 / gam);
        cf.ra = (float)gam;
        cf.rb = (float)(gam * c7);
        cf.f0 = (float)c12;
        cf.f1 = (float)c11;
        cf.f2 = (float)c10;
    }

    cudaFuncSetAttribute(logmap_mma_kernel,
                         cudaFuncAttributeMaxDynamicSharedMemorySize, SMEM_TOTAL);
    logmap_mma_kernel<<<nmat, 128, SMEM_TOTAL>>>(X, out, cf);
}

// round 15
// speedup vs baseline: 1.2089x; 1.1958x over previous
#include <cuda_runtime.h>
#include <cuda_bf16.h>
#include <math.h>
#include <stdint.h>

// LogMap via matrix polynomial on the tensor pipe (portable mma.sync m16n8k16 bf16).
// log(X) = p(S), S=(X-m I)/h on [1,6.8]; p = deg-8 Chebyshev fit.
// Sastre 3-product scheme: Z=S^2; W=Z*V, V=Z+c1*S; p = q*r + lin.
// Z is NEVER stored: V=Z(acc)+c1*S written directly; fused pass reconstructs
// Z = V - c1*S (both from SMEM -- no long-lived frag reuse, which R13/R14
// showed causes register spills). Two 8KB buffer pairs (32KB).
// 1 matrix/CTA, 4 warps; launch_bounds(128,5) -> 5 CTAs/SM (20 warps,
// the measured concurrency optimum from R7/R10 vs R11/R12).

#define DEG 8
struct Coeffs {
    float mshift, invh, c1;
    float qa, qb, qc, qd;       // q = qa*W + qb*Z + qc*S + qd*I   (scaled 1/gam)
    float ra, rb;               // r = ra*W + rb*S                 (scaled gam)
    float f0, f1, f2;           // lin = f0*I + f1*S + f2*Z
};

// smem: pair1 = S (hi,lo), pair2 = V -> r (hi,lo)
#define SH 0
#define SL 8192
#define VH 16384
#define VL 24576
#define SMEM_TOTAL 32768

__device__ __forceinline__ uint32_t smem_u32(const void* p) {
    uint32_t a;
    asm("{ .reg .u64 t; cvta.to.shared.u64 t, %1; cvt.u32.u64 %0, t; }"
        : "=r"(a) : "l"(p));
    return a;
}

__device__ __forceinline__ uint32_t swoff(int r, int cb) {
    return (uint32_t)(r * 128 + ((((cb >> 4) ^ (r & 7))) << 4) + (cb & 15));
}

__device__ __forceinline__ uint32_t lds32(uint32_t a) {
    uint32_t v;
    asm volatile("ld.shared.b32 %0, [%1];" : "=r"(v) : "r"(a));
    return v;
}
__device__ __forceinline__ void sts32(uint32_t a, uint32_t v) {
    asm volatile("st.shared.b32 [%0], %1;" :: "r"(a), "r"(v));
}
__device__ __forceinline__ void sts128(uint32_t a, uint32_t x, uint32_t y,
                                       uint32_t z, uint32_t w) {
    asm volatile("st.shared.v4.b32 [%0], {%1,%2,%3,%4};"
                 :: "r"(a), "r"(x), "r"(y), "r"(z), "r"(w));
}

#define LDMX4(d, addr) \
    asm volatile("ldmatrix.sync.aligned.m8n8.x4.shared.b16 {%0,%1,%2,%3}, [%4];" \
        : "=r"((d)[0]), "=r"((d)[1]), "=r"((d)[2]), "=r"((d)[3]) : "r"(addr))

#define LDMX4T(d, addr) \
    asm volatile("ldmatrix.sync.aligned.m8n8.x4.trans.shared.b16 {%0,%1,%2,%3}, [%4];" \
        : "=r"((d)[0]), "=r"((d)[1]), "=r"((d)[2]), "=r"((d)[3]) : "r"(addr))

#define MMA(c, a, b0v, b1v) \
    asm volatile("mma.sync.aligned.m16n8k16.row.col.f32.bf16.bf16.f32 " \
        "{%0,%1,%2,%3}, {%4,%5,%6,%7}, {%8,%9}, {%0,%1,%2,%3};" \
        : "+f"((c)[0]), "+f"((c)[1]), "+f"((c)[2]), "+f"((c)[3]) \
        : "r"((a)[0]), "r"((a)[1]), "r"((a)[2]), "r"((a)[3]), "r"(b0v), "r"(b1v))

__device__ __forceinline__ uint32_t pk(float a, float b) {
    __nv_bfloat162 t = __floats2bfloat162_rn(a, b);
    return *reinterpret_cast<uint32_t*>(&t);
}
__device__ __forceinline__ float2 upk(uint32_t u) {
    __nv_bfloat162 t = *reinterpret_cast<__nv_bfloat162*>(&u);
    return __bfloat1622float2(t);
}
__device__ __forceinline__ float bhi(float v) {
    return __bfloat162float(__float2bfloat16_rn(v));
}

__global__ void __launch_bounds__(128, 5)
logmap_mma_kernel(const float* __restrict__ X, float* __restrict__ out, Coeffs cf)
{
    extern __shared__ char smraw[];
    const uint32_t sb = smem_u32(smraw);
    const int tid = threadIdx.x;
    const int w = tid >> 5;              // warp owns rows [16w, 16w+16)
    const int l = tid & 31;
    const int sr = 16 * w;
    const int lq = l >> 2, lr = l & 3;
    const int lmr = l & 15;
    const int lmc16 = (l >> 4) & 1;
    const int key = lmr & 7;
    const size_t mb = (size_t)blockIdx.x * 4096;

    uint32_t colx[4];
    #pragma unroll
    for (int j = 0; j < 4; j++) colx[j] = (uint32_t)((((2*j + lmc16) ^ key)) << 4);
    const uint32_t arow = (uint32_t)((sr + lmr) * 128);
    const int er0 = sr + lq, er1 = er0 + 8;

    // ---- load X (half-row/thread), S = (X - m I)/h, write S hi/lo -> pair1 ----
    {
        const int row = sr + (l >> 1);
        const int c0 = 32 * (l & 1);
        const float4* xr = (const float4*)(X + mb + (size_t)row * 64 + c0);
        float v[32];
        #pragma unroll
        for (int q = 0; q < 8; q++) {
            float4 f = xr[q];
            v[4*q] = f.x; v[4*q+1] = f.y; v[4*q+2] = f.z; v[4*q+3] = f.w;
        }
        #pragma unroll
        for (int i = 0; i < 32; i++) {
            float t = v[i];
            if (c0 + i == row) t -= cf.mshift;
            v[i] = t * cf.invh;
        }
        #pragma unroll
        for (int q = 0; q < 4; q++) {
            uint32_t o = swoff(row, 2 * c0 + 16 * q);
            const float* p = v + 8 * q;
            sts128(sb + SH + o, pk(p[0], p[1]), pk(p[2], p[3]),
                                pk(p[4], p[5]), pk(p[6], p[7]));
            sts128(sb + SL + o,
                   pk(p[0]-bhi(p[0]), p[1]-bhi(p[1])),
                   pk(p[2]-bhi(p[2]), p[3]-bhi(p[3])),
                   pk(p[4]-bhi(p[4]), p[5]-bhi(p[5])),
                   pk(p[6]-bhi(p[6]), p[7]-bhi(p[7])));
        }
    }
    __syncthreads();                       // (1) S visible

    float acc[8][4];
    uint32_t ah[4][4], al[4][4];

    auto zacc = [&] {
        #pragma unroll
        for (int n = 0; n < 8; n++)
            #pragma unroll
            for (int q = 0; q < 4; q++) acc[n][q] = 0.f;
    };

    auto cvtA = [&] {
        #pragma unroll
        for (int kk = 0; kk < 4; kk++) {
            float c00 = acc[2*kk][0],   c01 = acc[2*kk][1];
            float c02 = acc[2*kk][2],   c03 = acc[2*kk][3];
            float d00 = acc[2*kk+1][0], d01 = acc[2*kk+1][1];
            float d02 = acc[2*kk+1][2], d03 = acc[2*kk+1][3];
            ah[kk][0] = pk(c00, c01); ah[kk][1] = pk(c02, c03);
            ah[kk][2] = pk(d00, d01); ah[kk][3] = pk(d02, d03);
            al[kk][0] = pk(c00 - bhi(c00), c01 - bhi(c01));
            al[kk][1] = pk(c02 - bhi(c02), c03 - bhi(c03));
            al[kk][2] = pk(d00 - bhi(d00), d01 - bhi(d01));
            al[kk][3] = pk(d02 - bhi(d02), d03 - bhi(d03));
        }
    };

    // acc += A(frags)*B(smem hi/lo)
    auto product = [&](uint32_t bhBase, uint32_t blBase) {
        #pragma unroll
        for (int kk = 0; kk < 4; kk++) {
            const uint32_t kbo = (uint32_t)((16*kk + lmr) * 128);
            #pragma unroll
            for (int j = 0; j < 4; j++) {
                uint32_t o = kbo + colx[j];
                uint32_t b[4];
                LDMX4T(b, bhBase + o);
                MMA(acc[2*j],   ah[kk], b[0], b[1]);
                MMA(acc[2*j+1], ah[kk], b[2], b[3]);
                MMA(acc[2*j],   al[kk], b[0], b[1]);
                MMA(acc[2*j+1], al[kk], b[2], b[3]);
                LDMX4T(b, blBase + o);
                MMA(acc[2*j],   ah[kk], b[0], b[1]);
                MMA(acc[2*j+1], ah[kk], b[2], b[3]);
            }
        }
    };

    // ---- P1: Z = S*S (A frags from smem) ----
    #pragma unroll
    for (int kk = 0; kk < 4; kk++) {
        uint32_t o = arow + colx[kk];
        LDMX4(ah[kk], sb + SH + o);
        LDMX4(al[kk], sb + SL + o);
    }
    zacc();
    product(sb + SH, sb + SL);
    cvtA();                                // A <- Z (never stored)

    // ---- V = Z(acc) + c1*S -> pair2 (own rows; pair2 fresh, no pre-sync) ----
    #pragma unroll
    for (int n = 0; n < 8; n++) {
        int cb = 16 * n + 4 * lr;
        uint32_t o0 = swoff(er0, cb), o1 = swoff(er1, cb);
        float2 s0 = upk(lds32(sb + SH + o0));
        float2 s0l = upk(lds32(sb + SL + o0));
        float2 s1 = upk(lds32(sb + SH + o1));
        float2 s1l = upk(lds32(sb + SL + o1));
        float a0 = acc[n][0] + cf.c1 * (s0.x + s0l.x);
        float a1 = acc[n][1] + cf.c1 * (s0.y + s0l.y);
        float a2 = acc[n][2] + cf.c1 * (s1.x + s1l.x);
        float a3 = acc[n][3] + cf.c1 * (s1.y + s1l.y);
        sts32(sb + VH + o0, pk(a0, a1));
        sts32(sb + VH + o1, pk(a2, a3));
        sts32(sb + VL + o0, pk(a0 - bhi(a0), a1 - bhi(a1)));
        sts32(sb + VL + o1, pk(a2 - bhi(a2), a3 - bhi(a3)));
    }
    __syncthreads();                       // (2) V visible

    // ---- P2: W = Z*V ----
    zacc();
    product(sb + VH, sb + VL);
    __syncthreads();                       // (3) all P2 reads of V done

    // ---- fused pass: q -> frags, r -> pair2 (over V, group-wise), lin -> acc ----
    #pragma unroll
    for (int g = 0; g < 4; g++) {
        uint32_t sh[4], sl[4], vh[4], vl[4];
        uint32_t o = arow + colx[g];
        LDMX4(sh, sb + SH + o);
        LDMX4(sl, sb + SL + o);
        LDMX4(vh, sb + VH + o);
        LDMX4(vl, sb + VL + o);
        #pragma unroll
        for (int q = 0; q < 4; q++) {
            float2 s1 = upk(sh[q]), s2 = upk(sl[q]);
            float2 v1 = upk(vh[q]), v2 = upk(vl[q]);
            float sx = s1.x + s2.x, sy = s1.y + s2.y;
            float vx = v1.x + v2.x, vy = v1.y + v2.y;
            float zx = vx - cf.c1 * sx, zy = vy - cf.c1 * sy;
            int n = 2 * g + (q >> 1), c = (q & 1) * 2;
            int row = (q & 1) ? er1 : er0;
            int col0 = 8 * n + 2 * lr;
            float w0 = acc[n][c], w1 = acc[n][c + 1];
            // q
            float q0 = cf.qa * w0 + cf.qb * zx + cf.qc * sx;
            float q1 = cf.qa * w1 + cf.qb * zy + cf.qc * sy;
            if (col0 == row)     q0 += cf.qd;
            if (col0 + 1 == row) q1 += cf.qd;
            ah[g][q] = pk(q0, q1);
            al[g][q] = pk(q0 - bhi(q0), q1 - bhi(q1));
            // r -> pair2 (same 16-col group g just read)
            float r0 = cf.ra * w0 + cf.rb * sx;
            float r1 = cf.ra * w1 + cf.rb * sy;
            uint32_t so = swoff(row, 16 * n + 4 * lr);
            sts32(sb + VH + so, pk(r0, r1));
            sts32(sb + VL + so, pk(r0 - bhi(r0), r1 - bhi(r1)));
            // lin -> acc (P3 init)
            float f0 = cf.f1 * sx + cf.f2 * zx;
            float f1 = cf.f1 * sy + cf.f2 * zy;
            if (col0 == row)     f0 += cf.f0;
            if (col0 + 1 == row) f1 += cf.f0;
            acc[n][c] = f0;
            acc[n][c + 1] = f1;
        }
    }
    __syncthreads();                       // (4) r visible

    // ---- P3: P = lin + q*r ----
    product(sb + VH, sb + VL);

    // ---- store result (fp32) ----
    #pragma unroll
    for (int n = 0; n < 8; n++) {
        int c0 = 8 * n + 2 * lr;
        *(float2*)(out + mb + (size_t)er0 * 64 + c0) =
            make_float2(acc[n][0], acc[n][1]);
        *(float2*)(out + mb + (size_t)er1 * 64 + c0) =
            make_float2(acc[n][2], acc[n][3]);
    }
}

extern "C" void kernel_launch(void* const* d_in, const int* in_sizes, int n_in,
                              void* d_out, int out_size)
{
    const float* X = (const float*)d_in[0];
    float* out = (float*)d_out;
    const int nmat = in_sizes[0] >> 12;

    Coeffs cf;
    {
        // Chebyshev coeffs of log on [1, 6.8] -> monomial p0..p8
        const double a = 1.0, b = 6.8;
        const double m = 0.5 * (a + b);
        const double hh = 0.5 * (b - a);
        const double w = hh / m;
        const double rho = (1.0 - sqrt(1.0 - w * w)) / w;

        double c[DEG + 1];
        c[0] = log(m) - log1p(rho * rho);
        double rp = 1.0;
        for (int k = 1; k <= DEG; k++) {
            rp *= rho;
            c[k] = 2.0 * ((k & 1) ? rp : -rp) / (double)k;
        }
        double p[DEG + 1], Tm2[DEG + 1], Tm1[DEG + 1], Tc[DEG + 1];
        for (int i = 0; i <= DEG; i++) { p[i] = 0.0; Tm2[i] = 0.0; Tm1[i] = 0.0; }
        Tm2[0] = 1.0; p[0] += c[0];
        Tm1[1] = 1.0; p[1] += c[1];
        for (int k = 2; k <= DEG; k++) {
            for (int i = 0; i <= DEG; i++) Tc[i] = 0.0;
            for (int i = 0; i < k; i++) Tc[i + 1] += 2.0 * Tm1[i];
            for (int i = 0; i <= k - 2; i++) Tc[i] -= Tm2[i];
            for (int i = 0; i <= k; i++) p[i] += c[k] * Tc[i];
            for (int i = 0; i <= DEG; i++) { Tm2[i] = Tm1[i]; Tm1[i] = Tc[i]; }
        }

        // Sastre 3-product scheme
        const double c1 = p[7] / (2.0 * p[8]);
        const double c3 = p[6] - p[8] * c1 * c1;
        const double c5 = p[4] - c1 * p[5] + c1 * c1 * c3;
        const double c7 = (p[3] - c1 * c5) / c3;
        const double c4 = p[5] - p[8] * c7 - c3 * c1;
        const double c10 = p[2] - c4 * c7;
        const double c11 = p[1] - c5 * c7;
        const double c12 = p[0];

        // balance q, r
        double maxq = 0.0, maxr = 0.0;
        for (int i = 0; i <= 2000; i++) {
            double t = -1.0 + 2.0 * i / 2000.0;
            double W = t*t*t*t + c1 * t*t*t;
            double qv = p[8]*W + c3*t*t + c4*t + c5;
            double rv = W + c7*t;
            if (fabs(qv) > maxq) maxq = fabs(qv);
            if (fabs(rv) > maxr) maxr = fabs(rv);
        }
        const double gam = sqrt(maxq / maxr);

        cf.mshift = (float)m;
        cf.invh = (float)(1.0 / hh);
        cf.c1 = (float)c1;
        cf.qa = (float)(p[8] / gam);
        cf.qb = (float)(c3 / gam);
        cf.qc = (float)(c4 / gam);
        cf.qd = (float)(c5 / gam);
        cf.ra = (float)gam;
        cf.rb = (float)(gam * c7);
        cf.f0 = (float)c12;
        cf.f1 = (float)c11;
        cf.f2 = (float)c10;
    }

    cudaFuncSetAttribute(logmap_mma_kernel,
                         cudaFuncAttributeMaxDynamicSharedMemorySize, SMEM_TOTAL);
    logmap_mma_kernel<<<nmat, 128, SMEM_TOTAL>>>(X, out, cf);
}

// round 16
// speedup vs baseline: 1.2093x; 1.0003x over previous
#include <cuda_runtime.h>
#include <cuda_bf16.h>
#include <math.h>
#include <stdint.h>

// LogMap via matrix polynomial on the tensor pipe (portable mma.sync m16n8k16 bf16).
// log(X) = p(S), S=(X-m I)/h on [1,6.8]; p = deg-8 Chebyshev fit.
// Sastre 3-product scheme: Z=S^2; W=Z*V, V=Z+c1*S; p = q*r + lin.
// Z never stored; fused pass reconstructs Z = V - c1*S from SMEM.
// R16 change: fully COALESCED X-load (16B chunk per lane, warp=512B contig).
// The old per-row float4 load touched 32 distinct 128B lines per instruction
// (~512 L1 wavefronts/warp -- more than all 3 MMA products combined).
// 1 matrix/CTA, 4 warps; launch_bounds(128,5) -> 5 CTAs/SM (20 warps).

#define DEG 8
struct Coeffs {
    float mshift, invh, c1;
    float qa, qb, qc, qd;       // q = qa*W + qb*Z + qc*S + qd*I   (scaled 1/gam)
    float ra, rb;               // r = ra*W + rb*S                 (scaled gam)
    float f0, f1, f2;           // lin = f0*I + f1*S + f2*Z
};

// smem: pair1 = S (hi,lo), pair2 = V -> r (hi,lo)
#define SH 0
#define SL 8192
#define VH 16384
#define VL 24576
#define SMEM_TOTAL 32768

__device__ __forceinline__ uint32_t smem_u32(const void* p) {
    uint32_t a;
    asm("{ .reg .u64 t; cvta.to.shared.u64 t, %1; cvt.u32.u64 %0, t; }"
        : "=r"(a) : "l"(p));
    return a;
}

__device__ __forceinline__ uint32_t swoff(int r, int cb) {
    return (uint32_t)(r * 128 + ((((cb >> 4) ^ (r & 7))) << 4) + (cb & 15));
}

__device__ __forceinline__ uint32_t lds32(uint32_t a) {
    uint32_t v;
    asm volatile("ld.shared.b32 %0, [%1];" : "=r"(v) : "r"(a));
    return v;
}
__device__ __forceinline__ void sts32(uint32_t a, uint32_t v) {
    asm volatile("st.shared.b32 [%0], %1;" :: "r"(a), "r"(v));
}
__device__ __forceinline__ void sts64(uint32_t a, uint32_t x, uint32_t y) {
    asm volatile("st.shared.v2.b32 [%0], {%1,%2};" :: "r"(a), "r"(x), "r"(y));
}

#define LDMX4(d, addr) \
    asm volatile("ldmatrix.sync.aligned.m8n8.x4.shared.b16 {%0,%1,%2,%3}, [%4];" \
        : "=r"((d)[0]), "=r"((d)[1]), "=r"((d)[2]), "=r"((d)[3]) : "r"(addr))

#define LDMX4T(d, addr) \
    asm volatile("ldmatrix.sync.aligned.m8n8.x4.trans.shared.b16 {%0,%1,%2,%3}, [%4];" \
        : "=r"((d)[0]), "=r"((d)[1]), "=r"((d)[2]), "=r"((d)[3]) : "r"(addr))

#define MMA(c, a, b0v, b1v) \
    asm volatile("mma.sync.aligned.m16n8k16.row.col.f32.bf16.bf16.f32 " \
        "{%0,%1,%2,%3}, {%4,%5,%6,%7}, {%8,%9}, {%0,%1,%2,%3};" \
        : "+f"((c)[0]), "+f"((c)[1]), "+f"((c)[2]), "+f"((c)[3]) \
        : "r"((a)[0]), "r"((a)[1]), "r"((a)[2]), "r"((a)[3]), "r"(b0v), "r"(b1v))

__device__ __forceinline__ uint32_t pk(float a, float b) {
    __nv_bfloat162 t = __floats2bfloat162_rn(a, b);
    return *reinterpret_cast<uint32_t*>(&t);
}
__device__ __forceinline__ float2 upk(uint32_t u) {
    __nv_bfloat162 t = *reinterpret_cast<__nv_bfloat162*>(&u);
    return __bfloat1622float2(t);
}
__device__ __forceinline__ float bhi(float v) {
    return __bfloat162float(__float2bfloat16_rn(v));
}

__global__ void __launch_bounds__(128, 5)
logmap_mma_kernel(const float* __restrict__ X, float* __restrict__ out, Coeffs cf)
{
    extern __shared__ char smraw[];
    const uint32_t sb = smem_u32(smraw);
    const int tid = threadIdx.x;
    const int w = tid >> 5;              // warp owns rows [16w, 16w+16)
    const int l = tid & 31;
    const int sr = 16 * w;
    const int lq = l >> 2, lr = l & 3;
    const int lmr = l & 15;
    const int lmc16 = (l >> 4) & 1;
    const int key = lmr & 7;
    const size_t mb = (size_t)blockIdx.x * 4096;

    uint32_t colx[4];
    #pragma unroll
    for (int j = 0; j < 4; j++) colx[j] = (uint32_t)((((2*j + lmc16) ^ key)) << 4);
    const uint32_t arow = (uint32_t)((sr + lmr) * 128);
    const int er0 = sr + lq, er1 = er0 + 8;

    // ---- COALESCED X load: 16B chunk per lane per iter; S=(X-mI)/h -> pair1 ----
    {
        const float4* xv = (const float4*)(X + mb);
        #pragma unroll
        for (int i = 0; i < 8; i++) {
            int c = i * 128 + tid;          // chunk index (16B units)
            float4 f = xv[c];
            int row = c >> 4;               // 4 floats per chunk, 16 chunks/row
            int cblk = c & 15;              // column block (4 floats)
            float v0 = f.x, v1 = f.y, v2 = f.z, v3 = f.w;
            if ((row >> 2) == cblk) {       // diagonal falls in this chunk
                int e = row & 3;
                if (e == 0) v0 -= cf.mshift;
                else if (e == 1) v1 -= cf.mshift;
                else if (e == 2) v2 -= cf.mshift;
                else v3 -= cf.mshift;
            }
            v0 *= cf.invh; v1 *= cf.invh; v2 *= cf.invh; v3 *= cf.invh;
            uint32_t o = swoff(row, cblk * 8);   // 8 bytes (4 bf16)
            sts64(sb + SH + o, pk(v0, v1), pk(v2, v3));
            sts64(sb + SL + o, pk(v0 - bhi(v0), v1 - bhi(v1)),
                               pk(v2 - bhi(v2), v3 - bhi(v3)));
        }
    }
    __syncthreads();                       // (1) S visible

    float acc[8][4];
    uint32_t ah[4][4], al[4][4];

    auto zacc = [&] {
        #pragma unroll
        for (int n = 0; n < 8; n++)
            #pragma unroll
            for (int q = 0; q < 4; q++) acc[n][q] = 0.f;
    };

    auto cvtA = [&] {
        #pragma unroll
        for (int kk = 0; kk < 4; kk++) {
            float c00 = acc[2*kk][0],   c01 = acc[2*kk][1];
            float c02 = acc[2*kk][2],   c03 = acc[2*kk][3];
            float d00 = acc[2*kk+1][0], d01 = acc[2*kk+1][1];
            float d02 = acc[2*kk+1][2], d03 = acc[2*kk+1][3];
            ah[kk][0] = pk(c00, c01); ah[kk][1] = pk(c02, c03);
            ah[kk][2] = pk(d00, d01); ah[kk][3] = pk(d02, d03);
            al[kk][0] = pk(c00 - bhi(c00), c01 - bhi(c01));
            al[kk][1] = pk(c02 - bhi(c02), c03 - bhi(c03));
            al[kk][2] = pk(d00 - bhi(d00), d01 - bhi(d01));
            al[kk][3] = pk(d02 - bhi(d02), d03 - bhi(d03));
        }
    };

    // acc += A(frags)*B(smem hi/lo)
    auto product = [&](uint32_t bhBase, uint32_t blBase) {
        #pragma unroll
        for (int kk = 0; kk < 4; kk++) {
            const uint32_t kbo = (uint32_t)((16*kk + lmr) * 128);
            #pragma unroll
            for (int j = 0; j < 4; j++) {
                uint32_t o = kbo + colx[j];
                uint32_t b[4];
                LDMX4T(b, bhBase + o);
                MMA(acc[2*j],   ah[kk], b[0], b[1]);
                MMA(acc[2*j+1], ah[kk], b[2], b[3]);
                MMA(acc[2*j],   al[kk], b[0], b[1]);
                MMA(acc[2*j+1], al[kk], b[2], b[3]);
                LDMX4T(b, blBase + o);
                MMA(acc[2*j],   ah[kk], b[0], b[1]);
                MMA(acc[2*j+1], ah[kk], b[2], b[3]);
            }
        }
    };

    // ---- P1: Z = S*S (A frags from smem) ----
    #pragma unroll
    for (int kk = 0; kk < 4; kk++) {
        uint32_t o = arow + colx[kk];
        LDMX4(ah[kk], sb + SH + o);
        LDMX4(al[kk], sb + SL + o);
    }
    zacc();
    product(sb + SH, sb + SL);
    cvtA();                                // A <- Z (never stored)

    // ---- V = Z(acc) + c1*S -> pair2 (own rows; pair2 fresh, no pre-sync) ----
    #pragma unroll
    for (int n = 0; n < 8; n++) {
        int cb = 16 * n + 4 * lr;
        uint32_t o0 = swoff(er0, cb), o1 = swoff(er1, cb);
        float2 s0 = upk(lds32(sb + SH + o0));
        float2 s0l = upk(lds32(sb + SL + o0));
        float2 s1 = upk(lds32(sb + SH + o1));
        float2 s1l = upk(lds32(sb + SL + o1));
        float a0 = acc[n][0] + cf.c1 * (s0.x + s0l.x);
        float a1 = acc[n][1] + cf.c1 * (s0.y + s0l.y);
        float a2 = acc[n][2] + cf.c1 * (s1.x + s1l.x);
        float a3 = acc[n][3] + cf.c1 * (s1.y + s1l.y);
        sts32(sb + VH + o0, pk(a0, a1));
        sts32(sb + VH + o1, pk(a2, a3));
        sts32(sb + VL + o0, pk(a0 - bhi(a0), a1 - bhi(a1)));
        sts32(sb + VL + o1, pk(a2 - bhi(a2), a3 - bhi(a3)));
    }
    __syncthreads();                       // (2) V visible

    // ---- P2: W = Z*V ----
    zacc();
    product(sb + VH, sb + VL);
    __syncthreads();                       // (3) all P2 reads of V done

    // ---- fused pass: q -> frags, r -> pair2 (over V, group-wise), lin -> acc ----
    #pragma unroll
    for (int g = 0; g < 4; g++) {
        uint32_t sh[4], sl[4], vh[4], vl[4];
        uint32_t o = arow + colx[g];
        LDMX4(sh, sb + SH + o);
        LDMX4(sl, sb + SL + o);
        LDMX4(vh, sb + VH + o);
        LDMX4(vl, sb + VL + o);
        #pragma unroll
        for (int q = 0; q < 4; q++) {
            float2 s1 = upk(sh[q]), s2 = upk(sl[q]);
            float2 v1 = upk(vh[q]), v2 = upk(vl[q]);
            float sx = s1.x + s2.x, sy = s1.y + s2.y;
            float vx = v1.x + v2.x, vy = v1.y + v2.y;
            float zx = vx - cf.c1 * sx, zy = vy - cf.c1 * sy;
            int n = 2 * g + (q >> 1), c = (q & 1) * 2;
            int row = (q & 1) ? er1 : er0;
            int col0 = 8 * n + 2 * lr;
            float w0 = acc[n][c], w1 = acc[n][c + 1];
            // q
            float q0 = cf.qa * w0 + cf.qb * zx + cf.qc * sx;
            float q1 = cf.qa * w1 + cf.qb * zy + cf.qc * sy;
            if (col0 == row)     q0 += cf.qd;
            if (col0 + 1 == row) q1 += cf.qd;
            ah[g][q] = pk(q0, q1);
            al[g][q] = pk(q0 - bhi(q0), q1 - bhi(q1));
            // r -> pair2 (same 16-col group g just read)
            float r0 = cf.ra * w0 + cf.rb * sx;
            float r1 = cf.ra * w1 + cf.rb * sy;
            uint32_t so = swoff(row, 16 * n + 4 * lr);
            sts32(sb + VH + so, pk(r0, r1));
            sts32(sb + VL + so, pk(r0 - bhi(r0), r1 - bhi(r1)));
            // lin -> acc (P3 init)
            float f0 = cf.f1 * sx + cf.f2 * zx;
            float f1 = cf.f1 * sy + cf.f2 * zy;
            if (col0 == row)     f0 += cf.f0;
            if (col0 + 1 == row) f1 += cf.f0;
            acc[n][c] = f0;
            acc[n][c + 1] = f1;
        }
    }
    __syncthreads();                       // (4) r visible

    // ---- P3: P = lin + q*r ----
    product(sb + VH, sb + VL);

    // ---- store result (fp32) ----
    #pragma unroll
    for (int n = 0; n < 8; n++) {
        int c0 = 8 * n + 2 * lr;
        *(float2*)(out + mb + (size_t)er0 * 64 + c0) =
            make_float2(acc[n][0], acc[n][1]);
        *(float2*)(out + mb + (size_t)er1 * 64 + c0) =
            make_float2(acc[n][2], acc[n][3]);
    }
}

extern "C" void kernel_launch(void* const* d_in, const int* in_sizes, int n_in,
                              void* d_out, int out_size)
{
    const float* X = (const float*)d_in[0];
    float* out = (float*)d_out;
    const int nmat = in_sizes[0] >> 12;

    Coeffs cf;
    {
        // Chebyshev coeffs of log on [1, 6.8] -> monomial p0..p8
        const double a = 1.0, b = 6.8;
        const double m = 0.5 * (a + b);
        const double hh = 0.5 * (b - a);
        const double w = hh / m;
        const double rho = (1.0 - sqrt(1.0 - w * w)) / w;

        double c[DEG + 1];
        c[0] = log(m) - log1p(rho * rho);
        double rp = 1.0;
        for (int k = 1; k <= DEG; k++) {
            rp *= rho;
            c[k] = 2.0 * ((k & 1) ? rp : -rp) / (double)k;
        }
        double p[DEG + 1], Tm2[DEG + 1], Tm1[DEG + 1], Tc[DEG + 1];
        for (int i = 0; i <= DEG; i++) { p[i] = 0.0; Tm2[i] = 0.0; Tm1[i] = 0.0; }
        Tm2[0] = 1.0; p[0] += c[0];
        Tm1[1] = 1.0; p[1] += c[1];
        for (int k = 2; k <= DEG; k++) {
            for (int i = 0; i <= DEG; i++) Tc[i] = 0.0;
            for (int i = 0; i < k; i++) Tc[i + 1] += 2.0 * Tm1[i];
            for (int i = 0; i <= k - 2; i++) Tc[i] -= Tm2[i];
            for (int i = 0; i <= k; i++) p[i] += c[k] * Tc[i];
            for (int i = 0; i <= DEG; i++) { Tm2[i] = Tm1[i]; Tm1[i] = Tc[i]; }
        }

        // Sastre 3-product scheme
        const double c1 = p[7] / (2.0 * p[8]);
        const double c3 = p[6] - p[8] * c1 * c1;
        const double c5 = p[4] - c1 * p[5] + c1 * c1 * c3;
        const double c7 = (p[3] - c1 * c5) / c3;
        const double c4 = p[5] - p[8] * c7 - c3 * c1;
        const double c10 = p[2] - c4 * c7;
        const double c11 = p[1] - c5 * c7;
        const double c12 = p[0];

        // balance q, r
        double maxq = 0.0, maxr = 0.0;
        for (int i = 0; i <= 2000; i++) {
            double t = -1.0 + 2.0 * i / 2000.0;
            double W = t*t*t*t + c1 * t*t*t;
            double qv = p[8]*W + c3*t*t + c4*t + c5;
            double rv = W + c7*t;
            if (fabs(qv) > maxq) maxq = fabs(qv);
            if (fabs(rv) > maxr) maxr = fabs(rv);
        }
        const double gam = sqrt(maxq / maxr);

        cf.mshift = (float)m;
        cf.invh = (float)(1.0 / hh);
        cf.c1 = (float)c1;
        cf.qa = (float)(p[8] / gam);
        cf.qb = (float)(c3 / gam);
        cf.qc = (float)(c4 / gam);
        cf.qd = (float)(c5 / gam);
        cf.ra = (float)gam;
        cf.rb = (float)(gam * c7);
        cf.f0 = (float)c12;
        cf.f1 = (float)c11;
        cf.f2 = (float)c10;
    }

    cudaFuncSetAttribute(logmap_mma_kernel,
                         cudaFuncAttributeMaxDynamicSharedMemorySize, SMEM_TOTAL);
    logmap_mma_kernel<<<nmat, 128, SMEM_TOTAL>>>(X, out, cf);
}

// round 17
// speedup vs baseline: 1.4011x; 1.1587x over previous
#include <cuda_runtime.h>
#include <cuda_fp16.h>
#include <math.h>
#include <stdint.h>

// LogMap via matrix polynomial on the tensor pipe (portable mma.sync m16n8k16 fp16).
// log(X) = p(S), S=(X-m I)/h on [1,6.8]; p = deg-8 Chebyshev fit.
// Sastre 3-product scheme: Z=S^2; W=Z*V, V=Z+c1*S; p = q*r + lin.
// fp16 hi/lo split (lo ~2^-12): P1 is 3-term; P2/P3 are 2-TERM
// (Ah*Bh + Al*Bh, dropping Ah*Bl ~1.4e-4 rel_F each) -> B-side lo never
// loaded in P2/P3 (LDSM -33%) and MMA count 288->224. r stored hi-only.
// Coalesced X load; Z never stored; no frag liveness across epilogues.
// 1 matrix/CTA, 4 warps; launch_bounds(128,5) -> 5 CTAs/SM (20 warps).

#define DEG 8
struct Coeffs {
    float mshift, invh, c1;
    float qa, qb, qc, qd;       // q = qa*W + qb*Z + qc*S + qd*I   (scaled 1/gam)
    float ra, rb;               // r = ra*W + rb*S                 (scaled gam)
    float f0, f1, f2;           // lin = f0*I + f1*S + f2*Z
};

// smem: S (hi,lo), V (hi,lo); r overwrites VH (hi-only)
#define SH 0
#define SL 8192
#define VH 16384
#define VL 24576
#define SMEM_TOTAL 32768

__device__ __forceinline__ uint32_t smem_u32(const void* p) {
    uint32_t a;
    asm("{ .reg .u64 t; cvta.to.shared.u64 t, %1; cvt.u32.u64 %0, t; }"
        : "=r"(a) : "l"(p));
    return a;
}

__device__ __forceinline__ uint32_t swoff(int r, int cb) {
    return (uint32_t)(r * 128 + ((((cb >> 4) ^ (r & 7))) << 4) + (cb & 15));
}

__device__ __forceinline__ uint32_t lds32(uint32_t a) {
    uint32_t v;
    asm volatile("ld.shared.b32 %0, [%1];" : "=r"(v) : "r"(a));
    return v;
}
__device__ __forceinline__ void sts32(uint32_t a, uint32_t v) {
    asm volatile("st.shared.b32 [%0], %1;" :: "r"(a), "r"(v));
}
__device__ __forceinline__ void sts64(uint32_t a, uint32_t x, uint32_t y) {
    asm volatile("st.shared.v2.b32 [%0], {%1,%2};" :: "r"(a), "r"(x), "r"(y));
}

#define LDMX4(d, addr) \
    asm volatile("ldmatrix.sync.aligned.m8n8.x4.shared.b16 {%0,%1,%2,%3}, [%4];" \
        : "=r"((d)[0]), "=r"((d)[1]), "=r"((d)[2]), "=r"((d)[3]) : "r"(addr))

#define LDMX4T(d, addr) \
    asm volatile("ldmatrix.sync.aligned.m8n8.x4.trans.shared.b16 {%0,%1,%2,%3}, [%4];" \
        : "=r"((d)[0]), "=r"((d)[1]), "=r"((d)[2]), "=r"((d)[3]) : "r"(addr))

#define MMA(c, a, b0v, b1v) \
    asm volatile("mma.sync.aligned.m16n8k16.row.col.f32.f16.f16.f32 " \
        "{%0,%1,%2,%3}, {%4,%5,%6,%7}, {%8,%9}, {%0,%1,%2,%3};" \
        : "+f"((c)[0]), "+f"((c)[1]), "+f"((c)[2]), "+f"((c)[3]) \
        : "r"((a)[0]), "r"((a)[1]), "r"((a)[2]), "r"((a)[3]), "r"(b0v), "r"(b1v))

__device__ __forceinline__ uint32_t pk(float a, float b) {
    __half2 t = __floats2half2_rn(a, b);
    return *reinterpret_cast<uint32_t*>(&t);
}
__device__ __forceinline__ float2 upk(uint32_t u) {
    __half2 t = *reinterpret_cast<__half2*>(&u);
    return __half22float2(t);
}
__device__ __forceinline__ float bhi(float v) {
    return __half2float(__float2half_rn(v));
}

__global__ void __launch_bounds__(128, 5)
logmap_mma_kernel(const float* __restrict__ X, float* __restrict__ out, Coeffs cf)
{
    extern __shared__ char smraw[];
    const uint32_t sb = smem_u32(smraw);
    const int tid = threadIdx.x;
    const int w = tid >> 5;              // warp owns rows [16w, 16w+16)
    const int l = tid & 31;
    const int sr = 16 * w;
    const int lq = l >> 2, lr = l & 3;
    const int lmr = l & 15;
    const int lmc16 = (l >> 4) & 1;
    const int key = lmr & 7;
    const size_t mb = (size_t)blockIdx.x * 4096;

    uint32_t colx[4];
    #pragma unroll
    for (int j = 0; j < 4; j++) colx[j] = (uint32_t)((((2*j + lmc16) ^ key)) << 4);
    const uint32_t arow = (uint32_t)((sr + lmr) * 128);
    const int er0 = sr + lq, er1 = er0 + 8;

    // ---- COALESCED X load: 16B chunk per lane per iter; S=(X-mI)/h -> pair1 ----
    {
        const float4* xv = (const float4*)(X + mb);
        #pragma unroll
        for (int i = 0; i < 8; i++) {
            int c = i * 128 + tid;          // chunk index (16B units)
            float4 f = xv[c];
            int row = c >> 4;
            int cblk = c & 15;
            float v0 = f.x, v1 = f.y, v2 = f.z, v3 = f.w;
            if ((row >> 2) == cblk) {
                int e = row & 3;
                if (e == 0) v0 -= cf.mshift;
                else if (e == 1) v1 -= cf.mshift;
                else if (e == 2) v2 -= cf.mshift;
                else v3 -= cf.mshift;
            }
            v0 *= cf.invh; v1 *= cf.invh; v2 *= cf.invh; v3 *= cf.invh;
            uint32_t o = swoff(row, cblk * 8);
            sts64(sb + SH + o, pk(v0, v1), pk(v2, v3));
            sts64(sb + SL + o, pk(v0 - bhi(v0), v1 - bhi(v1)),
                               pk(v2 - bhi(v2), v3 - bhi(v3)));
        }
    }
    __syncthreads();                       // (1) S visible

    float acc[8][4];
    uint32_t ah[4][4], al[4][4];

    auto zacc = [&] {
        #pragma unroll
        for (int n = 0; n < 8; n++)
            #pragma unroll
            for (int q = 0; q < 4; q++) acc[n][q] = 0.f;
    };

    auto cvtA = [&] {
        #pragma unroll
        for (int kk = 0; kk < 4; kk++) {
            float c00 = acc[2*kk][0],   c01 = acc[2*kk][1];
            float c02 = acc[2*kk][2],   c03 = acc[2*kk][3];
            float d00 = acc[2*kk+1][0], d01 = acc[2*kk+1][1];
            float d02 = acc[2*kk+1][2], d03 = acc[2*kk+1][3];
            ah[kk][0] = pk(c00, c01); ah[kk][1] = pk(c02, c03);
            ah[kk][2] = pk(d00, d01); ah[kk][3] = pk(d02, d03);
            al[kk][0] = pk(c00 - bhi(c00), c01 - bhi(c01));
            al[kk][1] = pk(c02 - bhi(c02), c03 - bhi(c03));
            al[kk][2] = pk(d00 - bhi(d00), d01 - bhi(d01));
            al[kk][3] = pk(d02 - bhi(d02), d03 - bhi(d03));
        }
    };

    // 3-term product: acc += Ah*Bh + Al*Bh + Ah*Bl  (P1 only)
    auto product3 = [&](uint32_t bhBase, uint32_t blBase) {
        #pragma unroll
        for (int kk = 0; kk < 4; kk++) {
            const uint32_t kbo = (uint32_t)((16*kk + lmr) * 128);
            #pragma unroll
            for (int j = 0; j < 4; j++) {
                uint32_t o = kbo + colx[j];
                uint32_t b[4];
                LDMX4T(b, bhBase + o);
                MMA(acc[2*j],   ah[kk], b[0], b[1]);
                MMA(acc[2*j+1], ah[kk], b[2], b[3]);
                MMA(acc[2*j],   al[kk], b[0], b[1]);
                MMA(acc[2*j+1], al[kk], b[2], b[3]);
                LDMX4T(b, blBase + o);
                MMA(acc[2*j],   ah[kk], b[0], b[1]);
                MMA(acc[2*j+1], ah[kk], b[2], b[3]);
            }
        }
    };

    // 2-term product: acc += Ah*Bh + Al*Bh  (B lo dropped; fp16 lo ~2^-12)
    auto product2 = [&](uint32_t bhBase) {
        #pragma unroll
        for (int kk = 0; kk < 4; kk++) {
            const uint32_t kbo = (uint32_t)((16*kk + lmr) * 128);
            #pragma unroll
            for (int j = 0; j < 4; j++) {
                uint32_t b[4];
                LDMX4T(b, bhBase + kbo + colx[j]);
                MMA(acc[2*j],   ah[kk], b[0], b[1]);
                MMA(acc[2*j+1], ah[kk], b[2], b[3]);
                MMA(acc[2*j],   al[kk], b[0], b[1]);
                MMA(acc[2*j+1], al[kk], b[2], b[3]);
            }
        }
    };

    // ---- P1: Z = S*S (3-term; A frags from smem) ----
    #pragma unroll
    for (int kk = 0; kk < 4; kk++) {
        uint32_t o = arow + colx[kk];
        LDMX4(ah[kk], sb + SH + o);
        LDMX4(al[kk], sb + SL + o);
    }
    zacc();
    product3(sb + SH, sb + SL);
    cvtA();                                // A <- Z (never stored)

    // ---- V = Z(acc) + c1*S -> pair2 (own rows; pair2 fresh, no pre-sync) ----
    #pragma unroll
    for (int n = 0; n < 8; n++) {
        int cb = 16 * n + 4 * lr;
        uint32_t o0 = swoff(er0, cb), o1 = swoff(er1, cb);
        float2 s0 = upk(lds32(sb + SH + o0));
        float2 s0l = upk(lds32(sb + SL + o0));
        float2 s1 = upk(lds32(sb + SH + o1));
        float2 s1l = upk(lds32(sb + SL + o1));
        float a0 = acc[n][0] + cf.c1 * (s0.x + s0l.x);
        float a1 = acc[n][1] + cf.c1 * (s0.y + s0l.y);
        float a2 = acc[n][2] + cf.c1 * (s1.x + s1l.x);
        float a3 = acc[n][3] + cf.c1 * (s1.y + s1l.y);
        sts32(sb + VH + o0, pk(a0, a1));
        sts32(sb + VH + o1, pk(a2, a3));
        sts32(sb + VL + o0, pk(a0 - bhi(a0), a1 - bhi(a1)));
        sts32(sb + VL + o1, pk(a2 - bhi(a2), a3 - bhi(a3)));
    }
    __syncthreads();                       // (2) V visible

    // ---- P2: W = Z*V (2-term: V-hi only) ----
    zacc();
    product2(sb + VH);
    __syncthreads();                       // (3) all P2 reads of V done

    // ---- fused pass: q -> frags, r (hi-only) -> VH, lin -> acc ----
    // Exact V = vh + vl; Z = V - c1*S.
    #pragma unroll
    for (int g = 0; g < 4; g++) {
        uint32_t sh[4], sl[4], vh[4], vl[4];
        uint32_t o = arow + colx[g];
        LDMX4(sh, sb + SH + o);
        LDMX4(sl, sb + SL + o);
        LDMX4(vh, sb + VH + o);
        LDMX4(vl, sb + VL + o);
        #pragma unroll
        for (int q = 0; q < 4; q++) {
            float2 s1 = upk(sh[q]), s2 = upk(sl[q]);
            float2 v1 = upk(vh[q]), v2 = upk(vl[q]);
            float sx = s1.x + s2.x, sy = s1.y + s2.y;
            float vx = v1.x + v2.x, vy = v1.y + v2.y;
            float zx = vx - cf.c1 * sx, zy = vy - cf.c1 * sy;
            int n = 2 * g + (q >> 1), c = (q & 1) * 2;
            int row = (q & 1) ? er1 : er0;
            int col0 = 8 * n + 2 * lr;
            float w0 = acc[n][c], w1 = acc[n][c + 1];
            // q (hi+lo into frags)
            float q0 = cf.qa * w0 + cf.qb * zx + cf.qc * sx;
            float q1 = cf.qa * w1 + cf.qb * zy + cf.qc * sy;
            if (col0 == row)     q0 += cf.qd;
            if (col0 + 1 == row) q1 += cf.qd;
            ah[g][q] = pk(q0, q1);
            al[g][q] = pk(q0 - bhi(q0), q1 - bhi(q1));
            // r -> VH, hi only
            float r0 = cf.ra * w0 + cf.rb * sx;
            float r1 = cf.ra * w1 + cf.rb * sy;
            sts32(sb + VH + swoff(row, 16 * n + 4 * lr), pk(r0, r1));
            // lin -> acc (P3 init)
            float f0 = cf.f1 * sx + cf.f2 * zx;
            float f1 = cf.f1 * sy + cf.f2 * zy;
            if (col0 == row)     f0 += cf.f0;
            if (col0 + 1 == row) f1 += cf.f0;
            acc[n][c] = f0;
            acc[n][c + 1] = f1;
        }
    }
    __syncthreads();                       // (4) r visible

    // ---- P3: P = lin + q*r (2-term: r-hi only) ----
    product2(sb + VH);

    // ---- store result (fp32) ----
    #pragma unroll
    for (int n = 0; n < 8; n++) {
        int c0 = 8 * n + 2 * lr;
        *(float2*)(out + mb + (size_t)er0 * 64 + c0) =
            make_float2(acc[n][0], acc[n][1]);
        *(float2*)(out + mb + (size_t)er1 * 64 + c0) =
            make_float2(acc[n][2], acc[n][3]);
    }
}

extern "C" void kernel_launch(void* const* d_in, const int* in_sizes, int n_in,
                              void* d_out, int out_size)
{
    const float* X = (const float*)d_in[0];
    float* out = (float*)d_out;
    const int nmat = in_sizes[0] >> 12;

    Coeffs cf;
    {
        // Chebyshev coeffs of log on [1, 6.8] -> monomial p0..p8
        const double a = 1.0, b = 6.8;
        const double m = 0.5 * (a + b);
        const double hh = 0.5 * (b - a);
        const double w = hh / m;
        const double rho = (1.0 - sqrt(1.0 - w * w)) / w;

        double c[DEG + 1];
        c[0] = log(m) - log1p(rho * rho);
        double rp = 1.0;
        for (int k = 1; k <= DEG; k++) {
            rp *= rho;
            c[k] = 2.0 * ((k & 1) ? rp : -rp) / (double)k;
        }
        double p[DEG + 1], Tm2[DEG + 1], Tm1[DEG + 1], Tc[DEG + 1];
        for (int i = 0; i <= DEG; i++) { p[i] = 0.0; Tm2[i] = 0.0; Tm1[i] = 0.0; }
        Tm2[0] = 1.0; p[0] += c[0];
        Tm1[1] = 1.0; p[1] += c[1];
        for (int k = 2; k <= DEG; k++) {
            for (int i = 0; i <= DEG; i++) Tc[i] = 0.0;
            for (int i = 0; i < k; i++) Tc[i + 1] += 2.0 * Tm1[i];
            for (int i = 0; i <= k - 2; i++) Tc[i] -= Tm2[i];
            for (int i = 0; i <= k; i++) p[i] += c[k] * Tc[i];
            for (int i = 0; i <= DEG; i++) { Tm2[i] = Tm1[i]; Tm1[i] = Tc[i]; }
        }

        // Sastre 3-product scheme
        const double c1 = p[7] / (2.0 * p[8]);
        const double c3 = p[6] - p[8] * c1 * c1;
        const double c5 = p[4] - c1 * p[5] + c1 * c1 * c3;
        const double c7 = (p[3] - c1 * c5) / c3;
        const double c4 = p[5] - p[8] * c7 - c3 * c1;
        const double c10 = p[2] - c4 * c7;
        const double c11 = p[1] - c5 * c7;
        const double c12 = p[0];

        // balance q, r
        double maxq = 0.0, maxr = 0.0;
        for (int i = 0; i <= 2000; i++) {
            double t = -1.0 + 2.0 * i / 2000.0;
            double W = t*t*t*t + c1 * t*t*t;
            double qv = p[8]*W + c3*t*t + c4*t + c5;
            double rv = W + c7*t;
            if (fabs(qv) > maxq) maxq = fabs(qv);
            if (fabs(rv) > maxr) maxr = fabs(rv);
        }
        const double gam = sqrt(maxq / maxr);

        cf.mshift = (float)m;
        cf.invh = (float)(1.0 / hh);
        cf.c1 = (float)c1;
        cf.qa = (float)(p[8] / gam);
        cf.qb = (float)(c3 / gam);
        cf.qc = (float)(c4 / gam);
        cf.qd = (float)(c5 / gam);
        cf.ra = (float)gam;
        cf.rb = (float)(gam * c7);
        cf.f0 = (float)c12;
        cf.f1 = (float)c11;
        cf.f2 = (float)c10;
    }

    cudaFuncSetAttribute(logmap_mma_kernel,
                         cudaFuncAttributeMaxDynamicSharedMemorySize, SMEM_TOTAL);
    logmap_mma_kernel<<<nmat, 128, SMEM_TOTAL>>>(X, out, cf);
}